// round 7
// baseline (speedup 1.0000x reference)
#include <cuda_runtime.h>
#include <cuda_fp16.h>
#include <cstdint>
#include <math.h>

// Causal attention, B=4, S=4096, D=64, fp32 in/out.
// out = [ attn_vec (B*S*64) | attn_weights (B*S,S) ]
// fp16 datapath (same mantissa as tf32), mma.m16n8k16, fp32 accum.
// P never goes to smem: QK C-fragments are repacked in-register into PV
// A-fragments (warp tile 32 rows x 64 cols; PV partial over the 64-col k-slice).

constexpr int Bb = 4;
constexpr int Ss = 4096;
constexpr int Dh = 64;
constexpr int BQ = 128;
constexpr int BK = 128;
constexpr int NT = Ss / BQ;          // 32

// u32-word offsets in dynamic smem (fp16 data accessed as u32 words)
constexpr int OFFW_Q = 0;            // Qh [128][64] halves, pitch 32 words
constexpr int OFFW_K = 4096;         // Kh [128][64] halves, pitch 32 words
constexpr int OFFW_V = 8192;         // Vt [64][128] halves (d-major), pitch 64 words
constexpr int SMEM_WORDS = 12288;
constexpr int SMEM_BYTES = SMEM_WORDS * 4;   // 49152

__device__ float g_rsum[Bb * Ss];
__device__ float g_inv [Bb * Ss];
__device__ float g_vec [Bb * Ss * Dh];

__device__ __forceinline__ unsigned packh2(float lo, float hi) {
    __half2 h = __floats2half2_rn(lo, hi);
    return *(unsigned*)&h;
}

__device__ __forceinline__ void mma16(float& c0, float& c1, float& c2, float& c3,
                                      unsigned a0, unsigned a1, unsigned a2, unsigned a3,
                                      unsigned b0, unsigned b1) {
    asm("mma.sync.aligned.m16n8k16.row.col.f32.f16.f16.f32 "
        "{%0,%1,%2,%3}, {%4,%5,%6,%7}, {%8,%9}, {%0,%1,%2,%3};"
        : "+f"(c0), "+f"(c1), "+f"(c2), "+f"(c3)
        : "r"(a0), "r"(a1), "r"(a2), "r"(a3), "r"(b0), "r"(b1));
}

__global__ __launch_bounds__(256, 2)
void attn_score(const float* __restrict__ Q, const float* __restrict__ K,
                const float* __restrict__ V, float* __restrict__ out_w)
{
    extern __shared__ __align__(16) unsigned smu[];
    __half* smh = (__half*)smu;

    const int b  = blockIdx.y;
    const int x  = blockIdx.x;
    const int qt = x >> 5;
    const int kt = x & (NT - 1);
    const int q0 = qt * BQ, k0 = kt * BK;
    const int tid = threadIdx.x;

    if (kt > qt) {
        // strictly-upper tile: pure zero-fill of the weights region, then exit
        float* wg = out_w + ((size_t)(b * Ss + q0)) * Ss + k0;
        const float4 z = make_float4(0.f, 0.f, 0.f, 0.f);
        #pragma unroll
        for (int i = 0; i < 16; i++) {
            const int idx = tid + i * 256;
            const int row = idx >> 5;
            const int c4  = (idx & 31) << 2;
            *(float4*)(wg + (size_t)row * Ss + c4) = z;
        }
        return;
    }

    // ---- stage Q, K (fp16, swizzled, pitch 32 words) ----
    const float* Qg = Q + ((size_t)(b * Ss + q0)) * Dh;
    const float* Kg = K + ((size_t)(b * Ss + k0)) * Dh;
    const float* Vg = V + ((size_t)(b * Ss + k0)) * Dh;
    #pragma unroll
    for (int i = 0; i < 8; i++) {
        const int idx = tid + i * 256;
        const int row = idx >> 4;
        const int c4  = (idx & 15) << 2;
        const int w0  = c4 >> 1;                      // even
        const int swr = (row & 7) << 2;
        const int bw  = row * 32 + (w0 ^ swr);        // swizzle preserves +1 adjacency

        float4 q4 = *(const float4*)(Qg + row * Dh + c4);
        *(uint2*)(smu + OFFW_Q + bw) = make_uint2(packh2(q4.x, q4.y), packh2(q4.z, q4.w));

        float4 k4 = *(const float4*)(Kg + row * Dh + c4);
        *(uint2*)(smu + OFFW_K + bw) = make_uint2(packh2(k4.x, k4.y), packh2(k4.z, k4.w));
    }
    // ---- stage V transposed: Vt[d][k] halves, pitch 64 words, swizzled ----
    #pragma unroll
    for (int i = 0; i < 8; i++) {
        const int idx = tid + i * 256;
        const int k   = idx & 127;
        const int d4  = (idx >> 7) << 2;
        float4 v4 = *(const float4*)(Vg + k * Dh + d4);
        float vv[4] = {v4.x, v4.y, v4.z, v4.w};
        #pragma unroll
        for (int j = 0; j < 4; j++) {
            const int d = d4 + j;
            const int wv = (k >> 1) ^ ((d & 7) << 2);
            smh[((OFFW_V + d * 64 + wv) << 1) + (k & 1)] = __float2half_rn(vv[j]);
        }
    }
    __syncthreads();   // the only sync: staging complete

    const int w = tid >> 5, lane = tid & 31;
    const int grp = lane >> 2, tig = lane & 3;
    const int sw  = grp << 2;

    // ---- warp tile: rows 32 (wm in {0..3}), score cols 64 (wn in {0,1}) ----
    const int wm = w & 3, wn = w >> 2;

    // ---- QK^T: acc[m 0..1][an 0..7][4] ----
    float acc[2][8][4];
    #pragma unroll
    for (int i = 0; i < 2; i++)
        #pragma unroll
        for (int j = 0; j < 8; j++)
            #pragma unroll
            for (int c = 0; c < 4; c++) acc[i][j][c] = 0.0f;

    #pragma unroll
    for (int kk = 0; kk < 4; kk++) {
        const int w0 = kk * 8 + tig;
        unsigned ah[2][4];
        #pragma unroll
        for (int m = 0; m < 2; m++) {
            const int r = wm * 32 + m * 16 + grp;
            ah[m][0] = smu[OFFW_Q + r * 32 + (w0 ^ sw)];
            ah[m][1] = smu[OFFW_Q + (r + 8) * 32 + (w0 ^ sw)];
            ah[m][2] = smu[OFFW_Q + r * 32 + ((w0 + 4) ^ sw)];
            ah[m][3] = smu[OFFW_Q + (r + 8) * 32 + ((w0 + 4) ^ sw)];
        }
        unsigned bh[8][2];
        #pragma unroll
        for (int an = 0; an < 8; an++) {
            const int n = wn * 64 + an * 8 + grp;
            bh[an][0] = smu[OFFW_K + n * 32 + (w0 ^ sw)];
            bh[an][1] = smu[OFFW_K + n * 32 + ((w0 + 4) ^ sw)];
        }
        #pragma unroll
        for (int m = 0; m < 2; m++)
            #pragma unroll
            for (int an = 0; an < 8; an++) {
                float* c = acc[m][an];
                mma16(c[0], c[1], c[2], c[3],
                      ah[m][0], ah[m][1], ah[m][2], ah[m][3],
                      bh[an][0], bh[an][1]);
            }
    }

    // ---- mask + exp; write fp32 weights; rowsums (no smem involved) ----
    #pragma unroll
    for (int m = 0; m < 2; m++) {
        const int rowl = q0 + wm * 32 + m * 16 + grp;
        const int rowh = rowl + 8;
        float rlo = 0.0f, rhi = 0.0f;
        #pragma unroll
        for (int an = 0; an < 8; an++) {
            const int col = k0 + wn * 64 + an * 8 + 2 * tig;
            float* c = acc[m][an];
            float e0 = (col     <= rowl) ? __expf(c[0] * 0.125f) : 0.0f;
            float e1 = (col + 1 <= rowl) ? __expf(c[1] * 0.125f) : 0.0f;
            float e2 = (col     <= rowh) ? __expf(c[2] * 0.125f) : 0.0f;
            float e3 = (col + 1 <= rowh) ? __expf(c[3] * 0.125f) : 0.0f;
            c[0] = e0; c[1] = e1; c[2] = e2; c[3] = e3;
            rlo += e0 + e1; rhi += e2 + e3;

            float* wg = out_w + ((size_t)(b * Ss + rowl)) * Ss + col;
            *(float2*)wg                    = make_float2(e0, e1);
            *(float2*)(wg + (size_t)8 * Ss) = make_float2(e2, e3);
        }
        rlo += __shfl_xor_sync(0xffffffffu, rlo, 1);
        rlo += __shfl_xor_sync(0xffffffffu, rlo, 2);
        rhi += __shfl_xor_sync(0xffffffffu, rhi, 1);
        rhi += __shfl_xor_sync(0xffffffffu, rhi, 2);
        if (tig == 0) {
            atomicAdd(&g_rsum[b * Ss + rowl], rlo);
            atomicAdd(&g_rsum[b * Ss + rowh], rhi);
        }
    }

    // ---- pack exp'd scores into PV A-fragments (acc dies here) ----
    // PV k16-tile j uses score n-tiles 2j (k 16j..16j+7) and 2j+1 (k+8..15).
    unsigned pfrag[2][4][4];
    #pragma unroll
    for (int m = 0; m < 2; m++)
        #pragma unroll
        for (int j = 0; j < 4; j++) {
            pfrag[m][j][0] = packh2(acc[m][2*j][0],     acc[m][2*j][1]);
            pfrag[m][j][1] = packh2(acc[m][2*j][2],     acc[m][2*j][3]);
            pfrag[m][j][2] = packh2(acc[m][2*j + 1][0], acc[m][2*j + 1][1]);
            pfrag[m][j][3] = packh2(acc[m][2*j + 1][2], acc[m][2*j + 1][3]);
        }

    // ---- PV partial over this warp's 64-col k-slice; all 64 d ----
    float vacc[2][8][4];
    #pragma unroll
    for (int i = 0; i < 2; i++)
        #pragma unroll
        for (int j = 0; j < 8; j++)
            #pragma unroll
            for (int c = 0; c < 4; c++) vacc[i][j][c] = 0.0f;

    #pragma unroll
    for (int j = 0; j < 4; j++) {
        const int w0 = wn * 32 + j * 8 + tig;    // k-word within Vt row
        unsigned vb[8][2];
        #pragma unroll
        for (int an = 0; an < 8; an++) {
            const int d = an * 8 + grp;
            vb[an][0] = smu[OFFW_V + d * 64 + (w0 ^ sw)];
            vb[an][1] = smu[OFFW_V + d * 64 + ((w0 + 4) ^ sw)];
        }
        #pragma unroll
        for (int m = 0; m < 2; m++)
            #pragma unroll
            for (int an = 0; an < 8; an++) {
                float* c = vacc[m][an];
                mma16(c[0], c[1], c[2], c[3],
                      pfrag[m][j][0], pfrag[m][j][1], pfrag[m][j][2], pfrag[m][j][3],
                      vb[an][0], vb[an][1]);
            }
    }

    #pragma unroll
    for (int m = 0; m < 2; m++) {
        const int gl = b * Ss + q0 + wm * 32 + m * 16 + grp;
        const int gh = gl + 8;
        #pragma unroll
        for (int an = 0; an < 8; an++) {
            const int d = an * 8 + 2 * tig;
            float* c = vacc[m][an];
            atomicAdd(&g_vec[(size_t)gl * Dh + d],     c[0]);
            atomicAdd(&g_vec[(size_t)gl * Dh + d + 1], c[1]);
            atomicAdd(&g_vec[(size_t)gh * Dh + d],     c[2]);
            atomicAdd(&g_vec[(size_t)gh * Dh + d + 1], c[3]);
        }
    }
}

// vec = g_vec / rowsum ; also publish g_inv
__global__ __launch_bounds__(256)
void finalize(float* __restrict__ out_vec)
{
    const int idx = blockIdx.x * 256 + threadIdx.x;
    const int row = idx >> 4;
    const int c4  = (idx & 15) << 2;
    const float inv = 1.0f / g_rsum[row];
    if ((idx & 15) == 0) g_inv[row] = inv;
    float4 v = *(const float4*)(g_vec + (size_t)row * Dh + c4);
    v.x *= inv; v.y *= inv; v.z *= inv; v.w *= inv;
    *(float4*)(out_vec + (size_t)row * Dh + c4) = v;
}

// Scale causal tiles by 1/rowsum (tile-parallel; only kt<=qt tiles exist here).
__global__ __launch_bounds__(256)
void norm_w(float* __restrict__ w)
{
    const int b = blockIdx.y;
    const int x = blockIdx.x;

    int qt = (int)((sqrtf(8.0f * (float)x + 1.0f) - 1.0f) * 0.5f);
    while ((qt + 1) * (qt + 2) / 2 <= x) qt++;
    while (qt * (qt + 1) / 2 > x) qt--;
    const int kt = x - qt * (qt + 1) / 2;

    const int tid = threadIdx.x;
    float* wg = w + ((size_t)(b * Ss + qt * BQ)) * Ss + kt * BK;
    const float* invp = g_inv + b * Ss + qt * BQ;

    #pragma unroll
    for (int i = 0; i < 16; i++) {
        const int idx = tid + i * 256;
        const int row = idx >> 5;
        const int c4  = (idx & 31) << 2;
        const float inv = invp[row];
        float4 v = *(const float4*)(wg + (size_t)row * Ss + c4);
        v.x *= inv; v.y *= inv; v.z *= inv; v.w *= inv;
        *(float4*)(wg + (size_t)row * Ss + c4) = v;
    }
}

extern "C" void kernel_launch(void* const* d_in, const int* in_sizes, int n_in,
                              void* d_out, int out_size)
{
    const float* Q = (const float*)d_in[0];
    const float* K = (const float*)d_in[1];
    const float* V = (const float*)d_in[2];

    float* out_vec = (float*)d_out;
    float* out_w   = out_vec + (size_t)Bb * Ss * Dh;

    void* p_rsum = nullptr;
    void* p_vec  = nullptr;
    cudaGetSymbolAddress(&p_rsum, g_rsum);
    cudaGetSymbolAddress(&p_vec,  g_vec);
    cudaMemsetAsync(p_rsum, 0, sizeof(float) * Bb * Ss);
    cudaMemsetAsync(p_vec,  0, sizeof(float) * Bb * Ss * Dh);

    cudaFuncSetAttribute(attn_score, cudaFuncAttributeMaxDynamicSharedMemorySize,
                         SMEM_BYTES);

    dim3 gridA(NT * NT, Bb);                       // all (qt,kt); upper tiles zero-fill
    attn_score<<<gridA, 256, SMEM_BYTES>>>(Q, K, V, out_w);

    finalize<<<(Bb * Ss * Dh / 4) / 256, 256>>>(out_vec);

    const int ncausal = NT * (NT + 1) / 2;         // 528
    dim3 gridN(ncausal, Bb);
    norm_w<<<gridN, 256>>>(out_w);
}

// round 8
// speedup vs baseline: 1.0256x; 1.0256x over previous
#include <cuda_runtime.h>
#include <cuda_fp16.h>
#include <cstdint>

// Causal attention, B=4, S=4096, D=64, fp32 in/out.
// out = [ attn_vec (B*S*64) | attn_weights (B*S*S) ]
// fp16 datapath, mma.m16n8k16, fp32 accum.
// kt-chunked: one CTA per (qt, chunk of <=4 kt tiles). Q staged once,
// PV accumulator and rowsums persist in registers across the chunk,
// atomics flushed once per CTA. QK done in two 16-col half-passes to
// keep live registers under the 128-reg / 2-CTA cap.

constexpr int Bb = 4;
constexpr int Ss = 4096;
constexpr int Dh = 64;
constexpr int BQ = 128;
constexpr int BK = 128;
constexpr int NT = Ss / BQ;          // 32
constexpr int CH = 4;                // kt tiles per chunk

// u32-word offsets in dynamic smem (fp16 data accessed as u32 words)
constexpr int OFFW_Q = 0;            // Qh [128][64] halves, pitch 32 words
constexpr int OFFW_K = 4096;         // Kh [128][64] halves, pitch 32 words
constexpr int OFFW_V = 8192;         // Vt [64][128] halves (d-major), pitch 64 words
constexpr int OFFW_P = 12288;        // Ph [128][128] halves, pitch 64 words
constexpr int SMEM_WORDS = 20480;
constexpr int SMEM_BYTES = SMEM_WORDS * 4;   // 81920

__device__ float g_rsum[Bb * Ss];
__device__ float g_inv [Bb * Ss];
__device__ float g_vec [Bb * Ss * Dh];

__device__ __forceinline__ unsigned packh2(float lo, float hi) {
    __half2 h = __floats2half2_rn(lo, hi);
    return *(unsigned*)&h;
}

__device__ __forceinline__ void mma16(float& c0, float& c1, float& c2, float& c3,
                                      unsigned a0, unsigned a1, unsigned a2, unsigned a3,
                                      unsigned b0, unsigned b1) {
    asm("mma.sync.aligned.m16n8k16.row.col.f32.f16.f16.f32 "
        "{%0,%1,%2,%3}, {%4,%5,%6,%7}, {%8,%9}, {%0,%1,%2,%3};"
        : "+f"(c0), "+f"(c1), "+f"(c2), "+f"(c3)
        : "r"(a0), "r"(a1), "r"(a2), "r"(a3), "r"(b0), "r"(b1));
}

__global__ __launch_bounds__(256, 2)
void attn_score(const float* __restrict__ Q, const float* __restrict__ K,
                const float* __restrict__ V, float* __restrict__ out_w)
{
    extern __shared__ __align__(16) unsigned smu[];
    __half* smh = (__half*)smu;

    const int cc  = blockIdx.x;      // chunk index 0..7
    const int qt  = blockIdx.y;      // 0..31
    const int b   = blockIdx.z;      // 0..3
    const int tid = threadIdx.x;

    if (cc > (qt >> 2)) {
        // unused chunk slot: zero-fill a share of the strictly-upper tiles
        int u = 0;
        for (int i = 0; i < qt; i++) u += 7 - (i >> 2);
        u += cc - (qt >> 2) - 1;                     // 0..111 per batch
        const float4 z = make_float4(0.f, 0.f, 0.f, 0.f);
        for (int t = u; t < 496; t += 112) {
            int tt = t, q2 = 0;
            for (; q2 < 32; q2++) { int cnt = 31 - q2; if (tt < cnt) break; tt -= cnt; }
            const int k2 = q2 + 1 + tt;
            float* wg = out_w + ((size_t)(b * Ss + q2 * BQ)) * Ss + k2 * BK;
            #pragma unroll
            for (int i = 0; i < 16; i++) {
                const int idx = tid + i * 256;
                const int row = idx >> 5;
                const int c4  = (idx & 31) << 2;
                *(float4*)(wg + (size_t)row * Ss + c4) = z;
            }
        }
        return;
    }

    const int q0  = qt * BQ;
    const int kt0 = cc * CH;
    const int kt1 = (kt0 + CH - 1 < qt) ? (kt0 + CH - 1) : qt;

    // ---- stage Q once (fp16, swizzled, pitch 32 words) ----
    const float* Qg = Q + ((size_t)(b * Ss + q0)) * Dh;
    #pragma unroll
    for (int i = 0; i < 8; i++) {
        const int idx = tid + i * 256;
        const int row = idx >> 4;
        const int c4  = (idx & 15) << 2;
        const int w0  = c4 >> 1;
        const int swr = (row & 7) << 2;
        float4 q4 = *(const float4*)(Qg + row * Dh + c4);
        *(uint2*)(smu + OFFW_Q + row * 32 + (w0 ^ swr)) =
            make_uint2(packh2(q4.x, q4.y), packh2(q4.z, q4.w));
    }

    const int w = tid >> 5, lane = tid & 31;
    const int grp = lane >> 2, tig = lane & 3;
    const int sw  = grp << 2;
    const int wm = w & 1,  wn = w >> 1;     // QK: 64-row band x 32-col group
    const int wm2 = w >> 1, wn2 = w & 1;    // PV: 32-row band x 32-d group

    // persistent accumulators
    float vacc[2][4][4];
    #pragma unroll
    for (int i = 0; i < 2; i++)
        #pragma unroll
        for (int j = 0; j < 4; j++)
            #pragma unroll
            for (int c = 0; c < 4; c++) vacc[i][j][c] = 0.0f;
    float rs[4][2];
    #pragma unroll
    for (int i = 0; i < 4; i++) { rs[i][0] = 0.0f; rs[i][1] = 0.0f; }

    for (int kt = kt0; kt <= kt1; kt++) {
        const int k0 = kt * BK;
        __syncthreads();   // prev iteration's P/V readers done

        // ---- stage K (pitch 32 words) and V transposed (pitch 64 words) ----
        const float* Kg = K + ((size_t)(b * Ss + k0)) * Dh;
        const float* Vg = V + ((size_t)(b * Ss + k0)) * Dh;
        #pragma unroll
        for (int i = 0; i < 8; i++) {
            const int idx = tid + i * 256;
            const int row = idx >> 4;
            const int c4  = (idx & 15) << 2;
            const int w0  = c4 >> 1;
            const int swr = (row & 7) << 2;
            float4 k4 = *(const float4*)(Kg + row * Dh + c4);
            *(uint2*)(smu + OFFW_K + row * 32 + (w0 ^ swr)) =
                make_uint2(packh2(k4.x, k4.y), packh2(k4.z, k4.w));
        }
        #pragma unroll
        for (int i = 0; i < 8; i++) {
            const int idx = tid + i * 256;
            const int k   = idx & 127;
            const int d4  = (idx >> 7) << 2;
            float4 v4 = *(const float4*)(Vg + k * Dh + d4);
            float vv[4] = {v4.x, v4.y, v4.z, v4.w};
            #pragma unroll
            for (int j = 0; j < 4; j++) {
                const int d  = d4 + j;
                const int wv = (k >> 1) ^ ((d & 7) << 2);
                smh[((OFFW_V + d * 64 + wv) << 1) + (k & 1)] = __float2half_rn(vv[j]);
            }
        }
        __syncthreads();

        // ---- QK^T + exp + weight store, in two 16-col half-passes ----
        #pragma unroll
        for (int h = 0; h < 2; h++) {
            float acc[4][2][4];
            #pragma unroll
            for (int i = 0; i < 4; i++)
                #pragma unroll
                for (int j = 0; j < 2; j++)
                    #pragma unroll
                    for (int c = 0; c < 4; c++) acc[i][j][c] = 0.0f;

            #pragma unroll
            for (int kk = 0; kk < 4; kk++) {
                const int w0 = kk * 8 + tig;
                unsigned ah[4][4];
                #pragma unroll
                for (int am = 0; am < 4; am++) {
                    const int r = wm * 64 + am * 16 + grp;
                    ah[am][0] = smu[OFFW_Q + r * 32 + (w0 ^ sw)];
                    ah[am][1] = smu[OFFW_Q + (r + 8) * 32 + (w0 ^ sw)];
                    ah[am][2] = smu[OFFW_Q + r * 32 + ((w0 + 4) ^ sw)];
                    ah[am][3] = smu[OFFW_Q + (r + 8) * 32 + ((w0 + 4) ^ sw)];
                }
                unsigned bh[2][2];
                #pragma unroll
                for (int a2 = 0; a2 < 2; a2++) {
                    const int n = wn * 32 + (h * 2 + a2) * 8 + grp;
                    bh[a2][0] = smu[OFFW_K + n * 32 + (w0 ^ sw)];
                    bh[a2][1] = smu[OFFW_K + n * 32 + ((w0 + 4) ^ sw)];
                }
                #pragma unroll
                for (int am = 0; am < 4; am++)
                    #pragma unroll
                    for (int a2 = 0; a2 < 2; a2++) {
                        float* c = acc[am][a2];
                        mma16(c[0], c[1], c[2], c[3],
                              ah[am][0], ah[am][1], ah[am][2], ah[am][3],
                              bh[a2][0], bh[a2][1]);
                    }
            }

            // mask + exp; stage fp16 P; write fp32 weights; accumulate rowsums
            #pragma unroll
            for (int am = 0; am < 4; am++) {
                const int rl_loc = wm * 64 + am * 16 + grp;
                const int rowl = q0 + rl_loc;
                const int rowh = rowl + 8;
                #pragma unroll
                for (int a2 = 0; a2 < 2; a2++) {
                    const int cl_loc = wn * 32 + (h * 2 + a2) * 8 + 2 * tig;
                    const int col = k0 + cl_loc;
                    float* c = acc[am][a2];
                    float e0 = (col     <= rowl) ? __expf(c[0] * 0.125f) : 0.0f;
                    float e1 = (col + 1 <= rowl) ? __expf(c[1] * 0.125f) : 0.0f;
                    float e2 = (col     <= rowh) ? __expf(c[2] * 0.125f) : 0.0f;
                    float e3 = (col + 1 <= rowh) ? __expf(c[3] * 0.125f) : 0.0f;
                    rs[am][0] += e0 + e1;
                    rs[am][1] += e2 + e3;

                    const int wcol = (cl_loc >> 1) ^ sw;
                    smu[OFFW_P + rl_loc * 64 + wcol]       = packh2(e0, e1);
                    smu[OFFW_P + (rl_loc + 8) * 64 + wcol] = packh2(e2, e3);

                    float* wg = out_w + ((size_t)(b * Ss + rowl)) * Ss + col;
                    *(float2*)wg                    = make_float2(e0, e1);
                    *(float2*)(wg + (size_t)8 * Ss) = make_float2(e2, e3);
                }
            }
        }
        __syncthreads();   // P fully staged

        // ---- PV accumulate into persistent vacc ----
        #pragma unroll
        for (int ks = 0; ks < 8; ks++) {
            const int w0 = ks * 8 + tig;
            unsigned pa[2][4];
            #pragma unroll
            for (int am = 0; am < 2; am++) {
                const int r = wm2 * 32 + am * 16 + grp;
                pa[am][0] = smu[OFFW_P + r * 64 + (w0 ^ sw)];
                pa[am][1] = smu[OFFW_P + (r + 8) * 64 + (w0 ^ sw)];
                pa[am][2] = smu[OFFW_P + r * 64 + ((w0 + 4) ^ sw)];
                pa[am][3] = smu[OFFW_P + (r + 8) * 64 + ((w0 + 4) ^ sw)];
            }
            unsigned vb[4][2];
            #pragma unroll
            for (int an = 0; an < 4; an++) {
                const int d = wn2 * 32 + an * 8 + grp;
                vb[an][0] = smu[OFFW_V + d * 64 + (w0 ^ sw)];
                vb[an][1] = smu[OFFW_V + d * 64 + ((w0 + 4) ^ sw)];
            }
            #pragma unroll
            for (int am = 0; am < 2; am++)
                #pragma unroll
                for (int an = 0; an < 4; an++) {
                    float* c = vacc[am][an];
                    mma16(c[0], c[1], c[2], c[3],
                          pa[am][0], pa[am][1], pa[am][2], pa[am][3],
                          vb[an][0], vb[an][1]);
                }
        }
    }

    // ---- flush rowsums (once per CTA) ----
    #pragma unroll
    for (int am = 0; am < 4; am++) {
        float rlo = rs[am][0], rhi = rs[am][1];
        rlo += __shfl_xor_sync(0xffffffffu, rlo, 1);
        rlo += __shfl_xor_sync(0xffffffffu, rlo, 2);
        rhi += __shfl_xor_sync(0xffffffffu, rhi, 1);
        rhi += __shfl_xor_sync(0xffffffffu, rhi, 2);
        if (tig == 0) {
            const int rowl = b * Ss + q0 + wm * 64 + am * 16 + grp;
            atomicAdd(&g_rsum[rowl],     rlo);
            atomicAdd(&g_rsum[rowl + 8], rhi);
        }
    }

    // ---- flush PV partials (once per CTA) ----
    #pragma unroll
    for (int am = 0; am < 2; am++) {
        const int gl = b * Ss + q0 + wm2 * 32 + am * 16 + grp;
        const int gh = gl + 8;
        #pragma unroll
        for (int an = 0; an < 4; an++) {
            const int d = wn2 * 32 + an * 8 + 2 * tig;
            float* c = vacc[am][an];
            atomicAdd(&g_vec[(size_t)gl * Dh + d],     c[0]);
            atomicAdd(&g_vec[(size_t)gl * Dh + d + 1], c[1]);
            atomicAdd(&g_vec[(size_t)gh * Dh + d],     c[2]);
            atomicAdd(&g_vec[(size_t)gh * Dh + d + 1], c[3]);
        }
    }
}

// vec = g_vec / rowsum ; also publish g_inv
__global__ __launch_bounds__(256)
void finalize(float* __restrict__ out_vec)
{
    const int idx = blockIdx.x * 256 + threadIdx.x;
    const int row = idx >> 4;
    const int c4  = (idx & 15) << 2;
    const float inv = 1.0f / g_rsum[row];
    if ((idx & 15) == 0) g_inv[row] = inv;
    float4 v = *(const float4*)(g_vec + (size_t)row * Dh + c4);
    v.x *= inv; v.y *= inv; v.z *= inv; v.w *= inv;
    *(float4*)(out_vec + (size_t)row * Dh + c4) = v;
}

// Scale causal tiles by 1/rowsum (tile-parallel; only kt<=qt tiles exist here).
__global__ __launch_bounds__(256)
void norm_w(float* __restrict__ w)
{
    const int b = blockIdx.y;
    const int x = blockIdx.x;

    int qt = (int)((sqrtf(8.0f * (float)x + 1.0f) - 1.0f) * 0.5f);
    while ((qt + 1) * (qt + 2) / 2 <= x) qt++;
    while (qt * (qt + 1) / 2 > x) qt--;
    const int kt = x - qt * (qt + 1) / 2;

    const int tid = threadIdx.x;
    float* wg = w + ((size_t)(b * Ss + qt * BQ)) * Ss + kt * BK;
    const float* invp = g_inv + b * Ss + qt * BQ;

    #pragma unroll
    for (int i = 0; i < 16; i++) {
        const int idx = tid + i * 256;
        const int row = idx >> 5;
        const int c4  = (idx & 31) << 2;
        const float inv = invp[row];
        float4 v = *(const float4*)(wg + (size_t)row * Ss + c4);
        v.x *= inv; v.y *= inv; v.z *= inv; v.w *= inv;
        *(float4*)(wg + (size_t)row * Ss + c4) = v;
    }
}

extern "C" void kernel_launch(void* const* d_in, const int* in_sizes, int n_in,
                              void* d_out, int out_size)
{
    const float* Q = (const float*)d_in[0];
    const float* K = (const float*)d_in[1];
    const float* V = (const float*)d_in[2];

    float* out_vec = (float*)d_out;
    float* out_w   = out_vec + (size_t)Bb * Ss * Dh;

    void* p_rsum = nullptr;
    void* p_vec  = nullptr;
    cudaGetSymbolAddress(&p_rsum, g_rsum);
    cudaGetSymbolAddress(&p_vec,  g_vec);
    cudaMemsetAsync(p_rsum, 0, sizeof(float) * Bb * Ss);
    cudaMemsetAsync(p_vec,  0, sizeof(float) * Bb * Ss * Dh);

    cudaFuncSetAttribute(attn_score, cudaFuncAttributeMaxDynamicSharedMemorySize,
                         SMEM_BYTES);

    dim3 gridA(8, NT, Bb);     // (chunk, qt, batch); unused slots zero-fill
    attn_score<<<gridA, 256, SMEM_BYTES>>>(Q, K, V, out_w);

    finalize<<<(Bb * Ss * Dh / 4) / 256, 256>>>(out_vec);

    const int ncausal = NT * (NT + 1) / 2;         // 528
    dim3 gridN(ncausal, Bb);
    norm_w<<<gridN, 256>>>(out_w);
}

// round 9
// speedup vs baseline: 1.1054x; 1.0778x over previous
#include <cuda_runtime.h>
#include <cuda_fp16.h>
#include <cstdint>
#include <math.h>

// Causal attention, B=4, S=4096, D=64, fp32 in/out.
// out = [ attn_vec (B*S*64) | attn_weights (B*S*S) ]
// R6 structure (one CTA per 128x128 tile pair, fp16 mma.m16n8k16) with all
// MMA fragment loads converted to ldmatrix.x4 (conflict-free via block-XOR
// swizzle). Numerics identical to R6.

constexpr int Bb = 4;
constexpr int Ss = 4096;
constexpr int Dh = 64;
constexpr int BQ = 128;
constexpr int BK = 128;
constexpr int NT = Ss / BQ;          // 32

// u32-word offsets in dynamic smem (fp16 data accessed as u32 words)
constexpr int OFFW_Q = 0;            // Qh [128][64] halves, pitch 32 words
constexpr int OFFW_K = 4096;         // Kh [128][64] halves, pitch 32 words
constexpr int OFFW_P = 0;            // Ph [128][128] halves, pitch 64 words (overlays Q+K)
constexpr int OFFW_V = 8192;         // Vt [64][128] halves (d-major), pitch 64 words
constexpr int SMEM_WORDS = 12288;
constexpr int SMEM_BYTES = SMEM_WORDS * 4;   // 49152

__device__ float g_rsum[Bb * Ss];
__device__ float g_inv [Bb * Ss];
__device__ float g_vec [Bb * Ss * Dh];

__device__ __forceinline__ unsigned packh2(float lo, float hi) {
    __half2 h = __floats2half2_rn(lo, hi);
    return *(unsigned*)&h;
}

__device__ __forceinline__ void mma16(float& c0, float& c1, float& c2, float& c3,
                                      unsigned a0, unsigned a1, unsigned a2, unsigned a3,
                                      unsigned b0, unsigned b1) {
    asm("mma.sync.aligned.m16n8k16.row.col.f32.f16.f16.f32 "
        "{%0,%1,%2,%3}, {%4,%5,%6,%7}, {%8,%9}, {%0,%1,%2,%3};"
        : "+f"(c0), "+f"(c1), "+f"(c2), "+f"(c3)
        : "r"(a0), "r"(a1), "r"(a2), "r"(a3), "r"(b0), "r"(b1));
}

__device__ __forceinline__ void ldsm4(unsigned& r0, unsigned& r1,
                                      unsigned& r2, unsigned& r3, unsigned addr) {
    asm volatile("ldmatrix.sync.aligned.m8n8.x4.shared.b16 {%0,%1,%2,%3}, [%4];"
                 : "=r"(r0), "=r"(r1), "=r"(r2), "=r"(r3) : "r"(addr));
}

__global__ __launch_bounds__(256, 2)
void attn_score(const float* __restrict__ Q, const float* __restrict__ K,
                const float* __restrict__ V, float* __restrict__ out_w)
{
    extern __shared__ __align__(16) unsigned smu[];
    __half* smh = (__half*)smu;

    const int b  = blockIdx.y;
    const int x  = blockIdx.x;
    const int qt = x >> 5;
    const int kt = x & (NT - 1);
    const int q0 = qt * BQ, k0 = kt * BK;
    const int tid = threadIdx.x;

    if (kt > qt) {
        // strictly-upper tile: pure zero-fill of the weights region, then exit
        float* wg = out_w + ((size_t)(b * Ss + q0)) * Ss + k0;
        const float4 z = make_float4(0.f, 0.f, 0.f, 0.f);
        #pragma unroll
        for (int i = 0; i < 16; i++) {
            const int idx = tid + i * 256;
            const int row = idx >> 5;
            const int c4  = (idx & 31) << 2;
            *(float4*)(wg + (size_t)row * Ss + c4) = z;
        }
        return;
    }

    // ---- stage Q, K (fp16, swizzled, pitch 32 words) ----
    const float* Qg = Q + ((size_t)(b * Ss + q0)) * Dh;
    const float* Kg = K + ((size_t)(b * Ss + k0)) * Dh;
    const float* Vg = V + ((size_t)(b * Ss + k0)) * Dh;
    #pragma unroll
    for (int i = 0; i < 8; i++) {
        const int idx = tid + i * 256;
        const int row = idx >> 4;
        const int c4  = (idx & 15) << 2;
        const int w0  = c4 >> 1;                      // even
        const int swr = (row & 7) << 2;
        const int bw  = row * 32 + (w0 ^ swr);        // swizzle preserves +1 adjacency

        float4 q4 = *(const float4*)(Qg + row * Dh + c4);
        *(uint2*)(smu + OFFW_Q + bw) = make_uint2(packh2(q4.x, q4.y), packh2(q4.z, q4.w));

        float4 k4 = *(const float4*)(Kg + row * Dh + c4);
        *(uint2*)(smu + OFFW_K + bw) = make_uint2(packh2(k4.x, k4.y), packh2(k4.z, k4.w));
    }
    // ---- stage V transposed: Vt[d][k] halves, pitch 64 words, swizzled ----
    #pragma unroll
    for (int i = 0; i < 8; i++) {
        const int idx = tid + i * 256;
        const int k   = idx & 127;
        const int d4  = (idx >> 7) << 2;
        float4 v4 = *(const float4*)(Vg + k * Dh + d4);
        float vv[4] = {v4.x, v4.y, v4.z, v4.w};
        #pragma unroll
        for (int j = 0; j < 4; j++) {
            const int d = d4 + j;
            const int wv = (k >> 1) ^ ((d & 7) << 2);
            smh[((OFFW_V + d * 64 + wv) << 1) + (k & 1)] = __float2half_rn(vv[j]);
        }
    }
    __syncthreads();   // staging complete

    const int w = tid >> 5, lane = tid & 31;
    const int grp = lane >> 2, tig = lane & 3;
    const int sw  = grp << 2;

    // ldmatrix lane roles
    const unsigned smb = (unsigned)__cvta_generic_to_shared(smu);
    const int lm = lane >> 3, li = lane & 7;     // matrix id, row-in-matrix
    const int lmA_r = (lm & 1) << 3;             // A/P: row offset (+0/+8)
    const int lmA_k = (lm >> 1) << 2;            // A/P: k word offset (+0/+4)
    const int lmB_r = (lm >> 1) << 3;            // B/V: row offset (+0/+8)
    const int lmB_k = (lm & 1) << 2;             // B/V: k word offset (+0/+4)

    // ---- QK^T: warp tile 64x32 (wm in {0,1}, wn in {0..3}) ----
    const int wm = w & 1, wn = w >> 1;
    float acc[4][4][4];
    #pragma unroll
    for (int i = 0; i < 4; i++)
        #pragma unroll
        for (int j = 0; j < 4; j++)
            #pragma unroll
            for (int c = 0; c < 4; c++) acc[i][j][c] = 0.0f;

    #pragma unroll
    for (int kk = 0; kk < 4; kk++) {
        unsigned ah[4][4];
        #pragma unroll
        for (int am = 0; am < 4; am++) {
            const int row = wm * 64 + am * 16 + lmA_r + li;
            const unsigned addr = smb +
                ((OFFW_Q + row * 32 + (((kk << 3) + lmA_k) ^ ((row & 7) << 2))) << 2);
            ldsm4(ah[am][0], ah[am][1], ah[am][2], ah[am][3], addr);
        }
        unsigned bh[4][2];
        #pragma unroll
        for (int g = 0; g < 2; g++) {
            const int row = wn * 32 + (g << 4) + lmB_r + li;
            const unsigned addr = smb +
                ((OFFW_K + row * 32 + (((kk << 3) + lmB_k) ^ ((row & 7) << 2))) << 2);
            ldsm4(bh[2*g][0], bh[2*g][1], bh[2*g+1][0], bh[2*g+1][1], addr);
        }
        #pragma unroll
        for (int am = 0; am < 4; am++)
            #pragma unroll
            for (int an = 0; an < 4; an++) {
                float* c = acc[am][an];
                mma16(c[0], c[1], c[2], c[3],
                      ah[am][0], ah[am][1], ah[am][2], ah[am][3],
                      bh[an][0], bh[an][1]);
            }
    }

    __syncthreads();   // QK reads of Qh/Kh done; Ph may overwrite

    // ---- mask + exp; stage fp16 P; write fp32 weights; rowsums ----
    #pragma unroll
    for (int am = 0; am < 4; am++) {
        const int rl_loc = wm * 64 + am * 16 + grp;
        const int rowl = q0 + rl_loc;
        const int rowh = rowl + 8;
        float rlo = 0.0f, rhi = 0.0f;
        #pragma unroll
        for (int an = 0; an < 4; an++) {
            const int cl_loc = wn * 32 + an * 8 + 2 * tig;
            const int col = k0 + cl_loc;
            float* c = acc[am][an];
            float e0 = (col     <= rowl) ? __expf(c[0] * 0.125f) : 0.0f;
            float e1 = (col + 1 <= rowl) ? __expf(c[1] * 0.125f) : 0.0f;
            float e2 = (col     <= rowh) ? __expf(c[2] * 0.125f) : 0.0f;
            float e3 = (col + 1 <= rowh) ? __expf(c[3] * 0.125f) : 0.0f;
            rlo += e0 + e1; rhi += e2 + e3;

            const int wcol = (cl_loc >> 1) ^ sw;
            smu[OFFW_P + rl_loc * 64 + wcol]       = packh2(e0, e1);
            smu[OFFW_P + (rl_loc + 8) * 64 + wcol] = packh2(e2, e3);

            float* wg = out_w + ((size_t)(b * Ss + rowl)) * Ss + col;
            *(float2*)wg                    = make_float2(e0, e1);
            *(float2*)(wg + (size_t)8 * Ss) = make_float2(e2, e3);
        }
        rlo += __shfl_xor_sync(0xffffffffu, rlo, 1);
        rlo += __shfl_xor_sync(0xffffffffu, rlo, 2);
        rhi += __shfl_xor_sync(0xffffffffu, rhi, 1);
        rhi += __shfl_xor_sync(0xffffffffu, rhi, 2);
        if (tig == 0) {
            atomicAdd(&g_rsum[b * Ss + rowl], rlo);
            atomicAdd(&g_rsum[b * Ss + rowh], rhi);
        }
    }
    __syncthreads();   // Ph fully staged

    // ---- PV partial: warp tile 32x32 (wm2 in {0..3}, wn2 in {0,1}) ----
    const int wm2 = w >> 1, wn2 = w & 1;
    float vacc[2][4][4];
    #pragma unroll
    for (int i = 0; i < 2; i++)
        #pragma unroll
        for (int j = 0; j < 4; j++)
            #pragma unroll
            for (int c = 0; c < 4; c++) vacc[i][j][c] = 0.0f;

    #pragma unroll
    for (int ks = 0; ks < 8; ks++) {
        unsigned pa[2][4];
        #pragma unroll
        for (int am = 0; am < 2; am++) {
            const int row = wm2 * 32 + am * 16 + lmA_r + li;
            const unsigned addr = smb +
                ((OFFW_P + row * 64 + (((ks << 3) + lmA_k) ^ ((row & 7) << 2))) << 2);
            ldsm4(pa[am][0], pa[am][1], pa[am][2], pa[am][3], addr);
        }
        unsigned vb[4][2];
        #pragma unroll
        for (int g = 0; g < 2; g++) {
            const int row = wn2 * 32 + (g << 4) + lmB_r + li;   // d index
            const unsigned addr = smb +
                ((OFFW_V + row * 64 + (((ks << 3) + lmB_k) ^ ((row & 7) << 2))) << 2);
            ldsm4(vb[2*g][0], vb[2*g][1], vb[2*g+1][0], vb[2*g+1][1], addr);
        }
        #pragma unroll
        for (int am = 0; am < 2; am++)
            #pragma unroll
            for (int an = 0; an < 4; an++) {
                float* c = vacc[am][an];
                mma16(c[0], c[1], c[2], c[3],
                      pa[am][0], pa[am][1], pa[am][2], pa[am][3],
                      vb[an][0], vb[an][1]);
            }
    }

    #pragma unroll
    for (int am = 0; am < 2; am++) {
        const int gl = b * Ss + q0 + wm2 * 32 + am * 16 + grp;
        const int gh = gl + 8;
        #pragma unroll
        for (int an = 0; an < 4; an++) {
            const int d = wn2 * 32 + an * 8 + 2 * tig;
            float* c = vacc[am][an];
            atomicAdd(&g_vec[(size_t)gl * Dh + d],     c[0]);
            atomicAdd(&g_vec[(size_t)gl * Dh + d + 1], c[1]);
            atomicAdd(&g_vec[(size_t)gh * Dh + d],     c[2]);
            atomicAdd(&g_vec[(size_t)gh * Dh + d + 1], c[3]);
        }
    }
}

// vec = g_vec / rowsum ; also publish g_inv
__global__ __launch_bounds__(256)
void finalize(float* __restrict__ out_vec)
{
    const int idx = blockIdx.x * 256 + threadIdx.x;
    const int row = idx >> 4;
    const int c4  = (idx & 15) << 2;
    const float inv = 1.0f / g_rsum[row];
    if ((idx & 15) == 0) g_inv[row] = inv;
    float4 v = *(const float4*)(g_vec + (size_t)row * Dh + c4);
    v.x *= inv; v.y *= inv; v.z *= inv; v.w *= inv;
    *(float4*)(out_vec + (size_t)row * Dh + c4) = v;
}

// Scale causal tiles by 1/rowsum (tile-parallel; only kt<=qt tiles exist here).
__global__ __launch_bounds__(256)
void norm_w(float* __restrict__ w)
{
    const int b = blockIdx.y;
    const int x = blockIdx.x;

    int qt = (int)((sqrtf(8.0f * (float)x + 1.0f) - 1.0f) * 0.5f);
    while ((qt + 1) * (qt + 2) / 2 <= x) qt++;
    while (qt * (qt + 1) / 2 > x) qt--;
    const int kt = x - qt * (qt + 1) / 2;

    const int tid = threadIdx.x;
    float* wg = w + ((size_t)(b * Ss + qt * BQ)) * Ss + kt * BK;
    const float* invp = g_inv + b * Ss + qt * BQ;

    #pragma unroll
    for (int i = 0; i < 16; i++) {
        const int idx = tid + i * 256;
        const int row = idx >> 5;
        const int c4  = (idx & 31) << 2;
        const float inv = invp[row];
        float4 v = *(const float4*)(wg + (size_t)row * Ss + c4);
        v.x *= inv; v.y *= inv; v.z *= inv; v.w *= inv;
        *(float4*)(wg + (size_t)row * Ss + c4) = v;
    }
}

extern "C" void kernel_launch(void* const* d_in, const int* in_sizes, int n_in,
                              void* d_out, int out_size)
{
    const float* Q = (const float*)d_in[0];
    const float* K = (const float*)d_in[1];
    const float* V = (const float*)d_in[2];

    float* out_vec = (float*)d_out;
    float* out_w   = out_vec + (size_t)Bb * Ss * Dh;

    void* p_rsum = nullptr;
    void* p_vec  = nullptr;
    cudaGetSymbolAddress(&p_rsum, g_rsum);
    cudaGetSymbolAddress(&p_vec,  g_vec);
    cudaMemsetAsync(p_rsum, 0, sizeof(float) * Bb * Ss);
    cudaMemsetAsync(p_vec,  0, sizeof(float) * Bb * Ss * Dh);

    cudaFuncSetAttribute(attn_score, cudaFuncAttributeMaxDynamicSharedMemorySize,
                         SMEM_BYTES);

    dim3 gridA(NT * NT, Bb);                       // all (qt,kt); upper tiles zero-fill
    attn_score<<<gridA, 256, SMEM_BYTES>>>(Q, K, V, out_w);

    finalize<<<(Bb * Ss * Dh / 4) / 256, 256>>>(out_vec);

    const int ncausal = NT * (NT + 1) / 2;         // 528
    dim3 gridN(ncausal, Bb);
    norm_w<<<gridN, 256>>>(out_w);
}

// round 10
// speedup vs baseline: 1.1390x; 1.0304x over previous
#include <cuda_runtime.h>
#include <cuda_fp16.h>
#include <cstdint>
#include <math.h>

// Causal attention, B=4, S=4096, D=64, fp32 in/out.
// out = [ attn_vec (B*S*64) | attn_weights (B*S*S) ]
// R9 structure (fp16 mma.m16n8k16 + ldmatrix) with coalesced store paths:
//  - weights written from smem P (fp16->fp32), full rows, STG.128
//  - g_vec partials staged to smem then row-coalesced atomicAdd

constexpr int Bb = 4;
constexpr int Ss = 4096;
constexpr int Dh = 64;
constexpr int BQ = 128;
constexpr int BK = 128;
constexpr int NT = Ss / BQ;          // 32

// u32-word offsets in dynamic smem
constexpr int OFFW_Q = 0;            // Qh [128][64] halves, pitch 32 words
constexpr int OFFW_K = 4096;         // Kh [128][64] halves, pitch 32 words
constexpr int OFFW_P = 0;            // Ph [128][128] halves, pitch 64 words (overlays Q+K)
                                     // later reused as vacc fp32 [128][64]
constexpr int OFFW_V = 8192;         // Vt [64][128] halves (d-major), pitch 64 words
constexpr int SMEM_WORDS = 12288;
constexpr int SMEM_BYTES = SMEM_WORDS * 4;   // 49152

__device__ float g_rsum[Bb * Ss];
__device__ float g_inv [Bb * Ss];
__device__ float g_vec [Bb * Ss * Dh];

__device__ __forceinline__ unsigned packh2(float lo, float hi) {
    __half2 h = __floats2half2_rn(lo, hi);
    return *(unsigned*)&h;
}

__device__ __forceinline__ void mma16(float& c0, float& c1, float& c2, float& c3,
                                      unsigned a0, unsigned a1, unsigned a2, unsigned a3,
                                      unsigned b0, unsigned b1) {
    asm("mma.sync.aligned.m16n8k16.row.col.f32.f16.f16.f32 "
        "{%0,%1,%2,%3}, {%4,%5,%6,%7}, {%8,%9}, {%0,%1,%2,%3};"
        : "+f"(c0), "+f"(c1), "+f"(c2), "+f"(c3)
        : "r"(a0), "r"(a1), "r"(a2), "r"(a3), "r"(b0), "r"(b1));
}

__device__ __forceinline__ void ldsm4(unsigned& r0, unsigned& r1,
                                      unsigned& r2, unsigned& r3, unsigned addr) {
    asm volatile("ldmatrix.sync.aligned.m8n8.x4.shared.b16 {%0,%1,%2,%3}, [%4];"
                 : "=r"(r0), "=r"(r1), "=r"(r2), "=r"(r3) : "r"(addr));
}

__global__ __launch_bounds__(256, 2)
void attn_score(const float* __restrict__ Q, const float* __restrict__ K,
                const float* __restrict__ V, float* __restrict__ out_w)
{
    extern __shared__ __align__(16) unsigned smu[];
    __half* smh = (__half*)smu;

    const int b  = blockIdx.y;
    const int x  = blockIdx.x;
    const int qt = x >> 5;
    const int kt = x & (NT - 1);
    const int q0 = qt * BQ, k0 = kt * BK;
    const int tid = threadIdx.x;

    if (kt > qt) {
        // strictly-upper tile: pure zero-fill of the weights region, then exit
        float* wg = out_w + ((size_t)(b * Ss + q0)) * Ss + k0;
        const float4 z = make_float4(0.f, 0.f, 0.f, 0.f);
        #pragma unroll
        for (int i = 0; i < 16; i++) {
            const int idx = tid + i * 256;
            const int row = idx >> 5;
            const int c4  = (idx & 31) << 2;
            *(float4*)(wg + (size_t)row * Ss + c4) = z;
        }
        return;
    }

    // ---- stage Q, K (fp16, swizzled, pitch 32 words) ----
    const float* Qg = Q + ((size_t)(b * Ss + q0)) * Dh;
    const float* Kg = K + ((size_t)(b * Ss + k0)) * Dh;
    const float* Vg = V + ((size_t)(b * Ss + k0)) * Dh;
    #pragma unroll
    for (int i = 0; i < 8; i++) {
        const int idx = tid + i * 256;
        const int row = idx >> 4;
        const int c4  = (idx & 15) << 2;
        const int w0  = c4 >> 1;                      // even
        const int swr = (row & 7) << 2;
        const int bw  = row * 32 + (w0 ^ swr);

        float4 q4 = *(const float4*)(Qg + row * Dh + c4);
        *(uint2*)(smu + OFFW_Q + bw) = make_uint2(packh2(q4.x, q4.y), packh2(q4.z, q4.w));

        float4 k4 = *(const float4*)(Kg + row * Dh + c4);
        *(uint2*)(smu + OFFW_K + bw) = make_uint2(packh2(k4.x, k4.y), packh2(k4.z, k4.w));
    }
    // ---- stage V transposed: Vt[d][k] halves, pitch 64 words, swizzled ----
    #pragma unroll
    for (int i = 0; i < 8; i++) {
        const int idx = tid + i * 256;
        const int k   = idx & 127;
        const int d4  = (idx >> 7) << 2;
        float4 v4 = *(const float4*)(Vg + k * Dh + d4);
        float vv[4] = {v4.x, v4.y, v4.z, v4.w};
        #pragma unroll
        for (int j = 0; j < 4; j++) {
            const int d = d4 + j;
            const int wv = (k >> 1) ^ ((d & 7) << 2);
            smh[((OFFW_V + d * 64 + wv) << 1) + (k & 1)] = __float2half_rn(vv[j]);
        }
    }
    __syncthreads();   // staging complete

    const int w = tid >> 5, lane = tid & 31;
    const int grp = lane >> 2, tig = lane & 3;
    const int sw  = grp << 2;

    // ldmatrix lane roles
    const unsigned smb = (unsigned)__cvta_generic_to_shared(smu);
    const int lm = lane >> 3, li = lane & 7;
    const int lmA_r = (lm & 1) << 3;
    const int lmA_k = (lm >> 1) << 2;
    const int lmB_r = (lm >> 1) << 3;
    const int lmB_k = (lm & 1) << 2;

    // ---- QK^T: warp tile 64x32 (wm in {0,1}, wn in {0..3}) ----
    const int wm = w & 1, wn = w >> 1;
    float acc[4][4][4];
    #pragma unroll
    for (int i = 0; i < 4; i++)
        #pragma unroll
        for (int j = 0; j < 4; j++)
            #pragma unroll
            for (int c = 0; c < 4; c++) acc[i][j][c] = 0.0f;

    #pragma unroll
    for (int kk = 0; kk < 4; kk++) {
        unsigned ah[4][4];
        #pragma unroll
        for (int am = 0; am < 4; am++) {
            const int row = wm * 64 + am * 16 + lmA_r + li;
            const unsigned addr = smb +
                ((OFFW_Q + row * 32 + (((kk << 3) + lmA_k) ^ ((row & 7) << 2))) << 2);
            ldsm4(ah[am][0], ah[am][1], ah[am][2], ah[am][3], addr);
        }
        unsigned bh[4][2];
        #pragma unroll
        for (int g = 0; g < 2; g++) {
            const int row = wn * 32 + (g << 4) + lmB_r + li;
            const unsigned addr = smb +
                ((OFFW_K + row * 32 + (((kk << 3) + lmB_k) ^ ((row & 7) << 2))) << 2);
            ldsm4(bh[2*g][0], bh[2*g][1], bh[2*g+1][0], bh[2*g+1][1], addr);
        }
        #pragma unroll
        for (int am = 0; am < 4; am++)
            #pragma unroll
            for (int an = 0; an < 4; an++) {
                float* c = acc[am][an];
                mma16(c[0], c[1], c[2], c[3],
                      ah[am][0], ah[am][1], ah[am][2], ah[am][3],
                      bh[an][0], bh[an][1]);
            }
    }

    __syncthreads();   // QK reads of Qh/Kh done; Ph may overwrite

    // ---- mask + exp; stage fp16 P; rowsums (weights written later from P) ----
    #pragma unroll
    for (int am = 0; am < 4; am++) {
        const int rl_loc = wm * 64 + am * 16 + grp;
        const int rowl = q0 + rl_loc;
        const int rowh = rowl + 8;
        float rlo = 0.0f, rhi = 0.0f;
        #pragma unroll
        for (int an = 0; an < 4; an++) {
            const int cl_loc = wn * 32 + an * 8 + 2 * tig;
            const int col = k0 + cl_loc;
            float* c = acc[am][an];
            float e0 = (col     <= rowl) ? __expf(c[0] * 0.125f) : 0.0f;
            float e1 = (col + 1 <= rowl) ? __expf(c[1] * 0.125f) : 0.0f;
            float e2 = (col     <= rowh) ? __expf(c[2] * 0.125f) : 0.0f;
            float e3 = (col + 1 <= rowh) ? __expf(c[3] * 0.125f) : 0.0f;
            rlo += e0 + e1; rhi += e2 + e3;

            const int wcol = (cl_loc >> 1) ^ sw;
            smu[OFFW_P + rl_loc * 64 + wcol]       = packh2(e0, e1);
            smu[OFFW_P + (rl_loc + 8) * 64 + wcol] = packh2(e2, e3);
        }
        rlo += __shfl_xor_sync(0xffffffffu, rlo, 1);
        rlo += __shfl_xor_sync(0xffffffffu, rlo, 2);
        rhi += __shfl_xor_sync(0xffffffffu, rhi, 1);
        rhi += __shfl_xor_sync(0xffffffffu, rhi, 2);
        if (tig == 0) {
            atomicAdd(&g_rsum[b * Ss + rowl], rlo);
            atomicAdd(&g_rsum[b * Ss + rowh], rhi);
        }
    }
    __syncthreads();   // Ph fully staged

    // ---- coalesced weight write: full rows from smem P (fp16->fp32) ----
    #pragma unroll
    for (int pass = 0; pass < 16; pass++) {
        const int rloc = pass * 8 + w;
        const int swp  = (rloc & 7) << 2;
        uint2 pw = *(const uint2*)(smu + OFFW_P + rloc * 64 + ((2 * lane) ^ swp));
        float2 f0 = __half22float2(*(__half2*)&pw.x);
        float2 f1 = __half22float2(*(__half2*)&pw.y);
        *(float4*)(out_w + ((size_t)(b * Ss + q0 + rloc)) * Ss + k0 + 4 * lane) =
            make_float4(f0.x, f0.y, f1.x, f1.y);
    }

    // ---- PV partial: warp tile 32x32 (wm2 in {0..3}, wn2 in {0,1}) ----
    const int wm2 = w >> 1, wn2 = w & 1;
    float vacc[2][4][4];
    #pragma unroll
    for (int i = 0; i < 2; i++)
        #pragma unroll
        for (int j = 0; j < 4; j++)
            #pragma unroll
            for (int c = 0; c < 4; c++) vacc[i][j][c] = 0.0f;

    #pragma unroll
    for (int ks = 0; ks < 8; ks++) {
        unsigned pa[2][4];
        #pragma unroll
        for (int am = 0; am < 2; am++) {
            const int row = wm2 * 32 + am * 16 + lmA_r + li;
            const unsigned addr = smb +
                ((OFFW_P + row * 64 + (((ks << 3) + lmA_k) ^ ((row & 7) << 2))) << 2);
            ldsm4(pa[am][0], pa[am][1], pa[am][2], pa[am][3], addr);
        }
        unsigned vb[4][2];
        #pragma unroll
        for (int g = 0; g < 2; g++) {
            const int row = wn2 * 32 + (g << 4) + lmB_r + li;   // d index
            const unsigned addr = smb +
                ((OFFW_V + row * 64 + (((ks << 3) + lmB_k) ^ ((row & 7) << 2))) << 2);
            ldsm4(vb[2*g][0], vb[2*g][1], vb[2*g+1][0], vb[2*g+1][1], addr);
        }
        #pragma unroll
        for (int am = 0; am < 2; am++)
            #pragma unroll
            for (int an = 0; an < 4; an++) {
                float* c = vacc[am][an];
                mma16(c[0], c[1], c[2], c[3],
                      pa[am][0], pa[am][1], pa[am][2], pa[am][3],
                      vb[an][0], vb[an][1]);
            }
    }

    __syncthreads();   // all PV reads of Ph done; reuse region for vacc fp32

    // ---- stage vacc to smem (swizzled 8-word blocks) ----
    float* vsm = (float*)smu + OFFW_P;   // [128][64] fp32
    #pragma unroll
    for (int am = 0; am < 2; am++) {
        const int rl = wm2 * 32 + am * 16 + grp;
        const int rh = rl + 8;
        #pragma unroll
        for (int an = 0; an < 4; an++) {
            const int d  = wn2 * 32 + an * 8 + 2 * tig;
            const int wl = d ^ (grp << 3);
            float* c = vacc[am][an];
            *(float2*)(vsm + rl * 64 + wl) = make_float2(c[0], c[1]);
            *(float2*)(vsm + rh * 64 + wl) = make_float2(c[2], c[3]);
        }
    }
    __syncthreads();

    // ---- row-coalesced atomic flush of vec partials ----
    #pragma unroll
    for (int pass = 0; pass < 8; pass++) {
        const int rloc = pass * 16 + w * 2 + (lane >> 4);
        const int f    = lane & 15;
        const int swv  = (rloc & 7) << 3;
        float* gv = g_vec + ((size_t)(b * Ss + q0 + rloc)) * Dh;
        #pragma unroll
        for (int j = 0; j < 4; j++) {
            float val = vsm[rloc * 64 + ((f + 16 * j) ^ swv)];
            atomicAdd(gv + f + 16 * j, val);
        }
    }
}

// vec = g_vec / rowsum ; also publish g_inv
__global__ __launch_bounds__(256)
void finalize(float* __restrict__ out_vec)
{
    const int idx = blockIdx.x * 256 + threadIdx.x;
    const int row = idx >> 4;
    const int c4  = (idx & 15) << 2;
    const float inv = 1.0f / g_rsum[row];
    if ((idx & 15) == 0) g_inv[row] = inv;
    float4 v = *(const float4*)(g_vec + (size_t)row * Dh + c4);
    v.x *= inv; v.y *= inv; v.z *= inv; v.w *= inv;
    *(float4*)(out_vec + (size_t)row * Dh + c4) = v;
}

// Scale causal tiles by 1/rowsum (tile-parallel; only kt<=qt tiles exist here).
__global__ __launch_bounds__(256)
void norm_w(float* __restrict__ w)
{
    const int b = blockIdx.y;
    const int x = blockIdx.x;

    int qt = (int)((sqrtf(8.0f * (float)x + 1.0f) - 1.0f) * 0.5f);
    while ((qt + 1) * (qt + 2) / 2 <= x) qt++;
    while (qt * (qt + 1) / 2 > x) qt--;
    const int kt = x - qt * (qt + 1) / 2;

    const int tid = threadIdx.x;
    float* wg = w + ((size_t)(b * Ss + qt * BQ)) * Ss + kt * BK;
    const float* invp = g_inv + b * Ss + qt * BQ;

    #pragma unroll
    for (int i = 0; i < 16; i++) {
        const int idx = tid + i * 256;
        const int row = idx >> 5;
        const int c4  = (idx & 31) << 2;
        const float inv = invp[row];
        float4 v = *(const float4*)(wg + (size_t)row * Ss + c4);
        v.x *= inv; v.y *= inv; v.z *= inv; v.w *= inv;
        *(float4*)(wg + (size_t)row * Ss + c4) = v;
    }
}

extern "C" void kernel_launch(void* const* d_in, const int* in_sizes, int n_in,
                              void* d_out, int out_size)
{
    const float* Q = (const float*)d_in[0];
    const float* K = (const float*)d_in[1];
    const float* V = (const float*)d_in[2];

    float* out_vec = (float*)d_out;
    float* out_w   = out_vec + (size_t)Bb * Ss * Dh;

    void* p_rsum = nullptr;
    void* p_vec  = nullptr;
    cudaGetSymbolAddress(&p_rsum, g_rsum);
    cudaGetSymbolAddress(&p_vec,  g_vec);
    cudaMemsetAsync(p_rsum, 0, sizeof(float) * Bb * Ss);
    cudaMemsetAsync(p_vec,  0, sizeof(float) * Bb * Ss * Dh);

    cudaFuncSetAttribute(attn_score, cudaFuncAttributeMaxDynamicSharedMemorySize,
                         SMEM_BYTES);

    dim3 gridA(NT * NT, Bb);                       // all (qt,kt); upper tiles zero-fill
    attn_score<<<gridA, 256, SMEM_BYTES>>>(Q, K, V, out_w);

    finalize<<<(Bb * Ss * Dh / 4) / 256, 256>>>(out_vec);

    const int ncausal = NT * (NT + 1) / 2;         // 528
    dim3 gridN(ncausal, Bb);
    norm_w<<<gridN, 256>>>(out_w);
}

// round 11
// speedup vs baseline: 1.2588x; 1.1052x over previous
#include <cuda_runtime.h>
#include <cuda_fp16.h>
#include <cstdint>
#include <math.h>

// Causal attention, B=4, S=4096, D=64, fp32 in/out.
// out = [ attn_vec (B*S*64) | attn_weights (B*S*S) ]
// fp16 mma.m16n8k16 + ldmatrix. Normalization fused into attn_score via a
// per-(b,qt) arrival counter: CTAs finish PV first, then wait for the full
// row's rowsum and write NORMALIZED weights directly. No norm_w pass.

constexpr int Bb = 4;
constexpr int Ss = 4096;
constexpr int Dh = 64;
constexpr int BQ = 128;
constexpr int BK = 128;
constexpr int NT = Ss / BQ;          // 32

// u32-word offsets in dynamic smem
constexpr int OFFW_Q  = 0;           // Qh [128][64] halves, pitch 32 words
constexpr int OFFW_K  = 4096;        // Kh [128][64] halves, pitch 32 words
constexpr int OFFW_P  = 0;           // Ph [128][128] halves, pitch 64 words (overlays Q+K)
constexpr int OFFW_V  = 8192;        // Vt [64][128] halves (d-major), pitch 64 words
constexpr int OFFW_VA = 12288;       // vacc fp32 [128][64] staging (separate from P!)
constexpr int SMEM_WORDS = 20480;
constexpr int SMEM_BYTES = SMEM_WORDS * 4;   // 81920

__device__ float g_rsum[Bb * Ss];
__device__ float g_vec [Bb * Ss * Dh];
__device__ int   g_cnt [Bb * NT];

__device__ __forceinline__ unsigned packh2(float lo, float hi) {
    __half2 h = __floats2half2_rn(lo, hi);
    return *(unsigned*)&h;
}

__device__ __forceinline__ void mma16(float& c0, float& c1, float& c2, float& c3,
                                      unsigned a0, unsigned a1, unsigned a2, unsigned a3,
                                      unsigned b0, unsigned b1) {
    asm("mma.sync.aligned.m16n8k16.row.col.f32.f16.f16.f32 "
        "{%0,%1,%2,%3}, {%4,%5,%6,%7}, {%8,%9}, {%0,%1,%2,%3};"
        : "+f"(c0), "+f"(c1), "+f"(c2), "+f"(c3)
        : "r"(a0), "r"(a1), "r"(a2), "r"(a3), "r"(b0), "r"(b1));
}

__device__ __forceinline__ void ldsm4(unsigned& r0, unsigned& r1,
                                      unsigned& r2, unsigned& r3, unsigned addr) {
    asm volatile("ldmatrix.sync.aligned.m8n8.x4.shared.b16 {%0,%1,%2,%3}, [%4];"
                 : "=r"(r0), "=r"(r1), "=r"(r2), "=r"(r3) : "r"(addr));
}

__global__ __launch_bounds__(256, 2)
void attn_score(const float* __restrict__ Q, const float* __restrict__ K,
                const float* __restrict__ V, float* __restrict__ out_w)
{
    extern __shared__ __align__(16) unsigned smu[];
    __half* smh = (__half*)smu;

    const int b  = blockIdx.y;
    const int x  = blockIdx.x;
    const int qt = x >> 5;
    const int kt = x & (NT - 1);
    const int q0 = qt * BQ, k0 = kt * BK;
    const int tid = threadIdx.x;

    if (kt > qt) {
        // strictly-upper tile: pure zero-fill of the weights region, then exit
        float* wg = out_w + ((size_t)(b * Ss + q0)) * Ss + k0;
        const float4 z = make_float4(0.f, 0.f, 0.f, 0.f);
        #pragma unroll
        for (int i = 0; i < 16; i++) {
            const int idx = tid + i * 256;
            const int row = idx >> 5;
            const int c4  = (idx & 31) << 2;
            *(float4*)(wg + (size_t)row * Ss + c4) = z;
        }
        return;
    }

    // ---- stage Q, K (fp16, swizzled, pitch 32 words) ----
    const float* Qg = Q + ((size_t)(b * Ss + q0)) * Dh;
    const float* Kg = K + ((size_t)(b * Ss + k0)) * Dh;
    const float* Vg = V + ((size_t)(b * Ss + k0)) * Dh;
    #pragma unroll
    for (int i = 0; i < 8; i++) {
        const int idx = tid + i * 256;
        const int row = idx >> 4;
        const int c4  = (idx & 15) << 2;
        const int w0  = c4 >> 1;
        const int swr = (row & 7) << 2;
        const int bw  = row * 32 + (w0 ^ swr);

        float4 q4 = *(const float4*)(Qg + row * Dh + c4);
        *(uint2*)(smu + OFFW_Q + bw) = make_uint2(packh2(q4.x, q4.y), packh2(q4.z, q4.w));

        float4 k4 = *(const float4*)(Kg + row * Dh + c4);
        *(uint2*)(smu + OFFW_K + bw) = make_uint2(packh2(k4.x, k4.y), packh2(k4.z, k4.w));
    }
    // ---- stage V transposed: Vt[d][k] halves, pitch 64 words, swizzled ----
    #pragma unroll
    for (int i = 0; i < 8; i++) {
        const int idx = tid + i * 256;
        const int k   = idx & 127;
        const int d4  = (idx >> 7) << 2;
        float4 v4 = *(const float4*)(Vg + k * Dh + d4);
        float vv[4] = {v4.x, v4.y, v4.z, v4.w};
        #pragma unroll
        for (int j = 0; j < 4; j++) {
            const int d = d4 + j;
            const int wv = (k >> 1) ^ ((d & 7) << 2);
            smh[((OFFW_V + d * 64 + wv) << 1) + (k & 1)] = __float2half_rn(vv[j]);
        }
    }
    __syncthreads();   // staging complete

    const int w = tid >> 5, lane = tid & 31;
    const int grp = lane >> 2, tig = lane & 3;
    const int sw  = grp << 2;

    // ldmatrix lane roles
    const unsigned smb = (unsigned)__cvta_generic_to_shared(smu);
    const int lm = lane >> 3, li = lane & 7;
    const int lmA_r = (lm & 1) << 3;
    const int lmA_k = (lm >> 1) << 2;
    const int lmB_r = (lm >> 1) << 3;
    const int lmB_k = (lm & 1) << 2;

    // ---- QK^T: warp tile 64x32 (wm in {0,1}, wn in {0..3}) ----
    const int wm = w & 1, wn = w >> 1;
    float acc[4][4][4];
    #pragma unroll
    for (int i = 0; i < 4; i++)
        #pragma unroll
        for (int j = 0; j < 4; j++)
            #pragma unroll
            for (int c = 0; c < 4; c++) acc[i][j][c] = 0.0f;

    #pragma unroll
    for (int kk = 0; kk < 4; kk++) {
        unsigned ah[4][4];
        #pragma unroll
        for (int am = 0; am < 4; am++) {
            const int row = wm * 64 + am * 16 + lmA_r + li;
            const unsigned addr = smb +
                ((OFFW_Q + row * 32 + (((kk << 3) + lmA_k) ^ ((row & 7) << 2))) << 2);
            ldsm4(ah[am][0], ah[am][1], ah[am][2], ah[am][3], addr);
        }
        unsigned bh[4][2];
        #pragma unroll
        for (int g = 0; g < 2; g++) {
            const int row = wn * 32 + (g << 4) + lmB_r + li;
            const unsigned addr = smb +
                ((OFFW_K + row * 32 + (((kk << 3) + lmB_k) ^ ((row & 7) << 2))) << 2);
            ldsm4(bh[2*g][0], bh[2*g][1], bh[2*g+1][0], bh[2*g+1][1], addr);
        }
        #pragma unroll
        for (int am = 0; am < 4; am++)
            #pragma unroll
            for (int an = 0; an < 4; an++) {
                float* c = acc[am][an];
                mma16(c[0], c[1], c[2], c[3],
                      ah[am][0], ah[am][1], ah[am][2], ah[am][3],
                      bh[an][0], bh[an][1]);
            }
    }

    __syncthreads();   // QK reads of Qh/Kh done; Ph may overwrite

    // ---- mask + exp; stage fp16 P; rowsum atomics ----
    #pragma unroll
    for (int am = 0; am < 4; am++) {
        const int rl_loc = wm * 64 + am * 16 + grp;
        const int rowl = q0 + rl_loc;
        const int rowh = rowl + 8;
        float rlo = 0.0f, rhi = 0.0f;
        #pragma unroll
        for (int an = 0; an < 4; an++) {
            const int cl_loc = wn * 32 + an * 8 + 2 * tig;
            const int col = k0 + cl_loc;
            float* c = acc[am][an];
            float e0 = (col     <= rowl) ? __expf(c[0] * 0.125f) : 0.0f;
            float e1 = (col + 1 <= rowl) ? __expf(c[1] * 0.125f) : 0.0f;
            float e2 = (col     <= rowh) ? __expf(c[2] * 0.125f) : 0.0f;
            float e3 = (col + 1 <= rowh) ? __expf(c[3] * 0.125f) : 0.0f;
            rlo += e0 + e1; rhi += e2 + e3;

            const int wcol = (cl_loc >> 1) ^ sw;
            smu[OFFW_P + rl_loc * 64 + wcol]       = packh2(e0, e1);
            smu[OFFW_P + (rl_loc + 8) * 64 + wcol] = packh2(e2, e3);
        }
        rlo += __shfl_xor_sync(0xffffffffu, rlo, 1);
        rlo += __shfl_xor_sync(0xffffffffu, rlo, 2);
        rhi += __shfl_xor_sync(0xffffffffu, rhi, 1);
        rhi += __shfl_xor_sync(0xffffffffu, rhi, 2);
        if (tig == 0) {
            atomicAdd(&g_rsum[b * Ss + rowl], rlo);
            atomicAdd(&g_rsum[b * Ss + rowh], rhi);
        }
    }
    __syncthreads();   // Ph staged; all warps' rowsum atomics issued & visible to block

    // publish this CTA's arrival (release: fence after block-wide visibility)
    if (tid == 0) {
        __threadfence();
        atomicAdd(&g_cnt[b * NT + qt], 1);
    }

    // ---- PV partial: warp tile 32x32 (wm2 in {0..3}, wn2 in {0,1}) ----
    const int wm2 = w >> 1, wn2 = w & 1;
    float vacc[2][4][4];
    #pragma unroll
    for (int i = 0; i < 2; i++)
        #pragma unroll
        for (int j = 0; j < 4; j++)
            #pragma unroll
            for (int c = 0; c < 4; c++) vacc[i][j][c] = 0.0f;

    #pragma unroll
    for (int ks = 0; ks < 8; ks++) {
        unsigned pa[2][4];
        #pragma unroll
        for (int am = 0; am < 2; am++) {
            const int row = wm2 * 32 + am * 16 + lmA_r + li;
            const unsigned addr = smb +
                ((OFFW_P + row * 64 + (((ks << 3) + lmA_k) ^ ((row & 7) << 2))) << 2);
            ldsm4(pa[am][0], pa[am][1], pa[am][2], pa[am][3], addr);
        }
        unsigned vb[4][2];
        #pragma unroll
        for (int g = 0; g < 2; g++) {
            const int row = wn2 * 32 + (g << 4) + lmB_r + li;   // d index
            const unsigned addr = smb +
                ((OFFW_V + row * 64 + (((ks << 3) + lmB_k) ^ ((row & 7) << 2))) << 2);
            ldsm4(vb[2*g][0], vb[2*g][1], vb[2*g+1][0], vb[2*g+1][1], addr);
        }
        #pragma unroll
        for (int am = 0; am < 2; am++)
            #pragma unroll
            for (int an = 0; an < 4; an++) {
                float* c = vacc[am][an];
                mma16(c[0], c[1], c[2], c[3],
                      pa[am][0], pa[am][1], pa[am][2], pa[am][3],
                      vb[an][0], vb[an][1]);
            }
    }

    // ---- stage vacc to its own smem region (swizzled 8-word blocks) ----
    float* vsm = (float*)smu + OFFW_VA;   // [128][64] fp32
    #pragma unroll
    for (int am = 0; am < 2; am++) {
        const int rl = wm2 * 32 + am * 16 + grp;
        const int rh = rl + 8;
        #pragma unroll
        for (int an = 0; an < 4; an++) {
            const int d  = wn2 * 32 + an * 8 + 2 * tig;
            const int wl = d ^ (grp << 3);
            float* c = vacc[am][an];
            *(float2*)(vsm + rl * 64 + wl) = make_float2(c[0], c[1]);
            *(float2*)(vsm + rh * 64 + wl) = make_float2(c[2], c[3]);
        }
    }
    __syncthreads();

    // ---- row-coalesced atomic flush of vec partials ----
    #pragma unroll
    for (int pass = 0; pass < 8; pass++) {
        const int rloc = pass * 16 + w * 2 + (lane >> 4);
        const int f    = lane & 15;
        const int swv  = (rloc & 7) << 3;
        float* gv = g_vec + ((size_t)(b * Ss + q0 + rloc)) * Dh;
        #pragma unroll
        for (int j = 0; j < 4; j++) {
            float val = vsm[rloc * 64 + ((f + 16 * j) ^ swv)];
            atomicAdd(gv + f + 16 * j, val);
        }
    }

    // ---- wait for the whole row's rowsums, then write normalized weights ----
    if (tid == 0) {
        const int target = qt + 1;
        while (atomicAdd(&g_cnt[b * NT + qt], 0) < target) __nanosleep(200);
        __threadfence();   // acquire: order subsequent g_rsum reads
    }
    __syncthreads();

    #pragma unroll
    for (int pass = 0; pass < 16; pass++) {
        const int rloc = pass * 8 + w;
        const float inv = 1.0f / __ldcg(&g_rsum[b * Ss + q0 + rloc]);
        const int swp = (rloc & 7) << 2;
        uint2 pw = *(const uint2*)(smu + OFFW_P + rloc * 64 + ((2 * lane) ^ swp));
        float2 f0 = __half22float2(*(__half2*)&pw.x);
        float2 f1 = __half22float2(*(__half2*)&pw.y);
        *(float4*)(out_w + ((size_t)(b * Ss + q0 + rloc)) * Ss + k0 + 4 * lane) =
            make_float4(f0.x * inv, f0.y * inv, f1.x * inv, f1.y * inv);
    }
}

// vec = g_vec / rowsum
__global__ __launch_bounds__(256)
void finalize(float* __restrict__ out_vec)
{
    const int idx = blockIdx.x * 256 + threadIdx.x;
    const int row = idx >> 4;
    const int c4  = (idx & 15) << 2;
    const float inv = 1.0f / g_rsum[row];
    float4 v = *(const float4*)(g_vec + (size_t)row * Dh + c4);
    v.x *= inv; v.y *= inv; v.z *= inv; v.w *= inv;
    *(float4*)(out_vec + (size_t)row * Dh + c4) = v;
}

extern "C" void kernel_launch(void* const* d_in, const int* in_sizes, int n_in,
                              void* d_out, int out_size)
{
    const float* Q = (const float*)d_in[0];
    const float* K = (const float*)d_in[1];
    const float* V = (const float*)d_in[2];

    float* out_vec = (float*)d_out;
    float* out_w   = out_vec + (size_t)Bb * Ss * Dh;

    void* p_rsum = nullptr;
    void* p_vec  = nullptr;
    void* p_cnt  = nullptr;
    cudaGetSymbolAddress(&p_rsum, g_rsum);
    cudaGetSymbolAddress(&p_vec,  g_vec);
    cudaGetSymbolAddress(&p_cnt,  g_cnt);
    cudaMemsetAsync(p_rsum, 0, sizeof(float) * Bb * Ss);
    cudaMemsetAsync(p_vec,  0, sizeof(float) * Bb * Ss * Dh);
    cudaMemsetAsync(p_cnt,  0, sizeof(int) * Bb * NT);

    cudaFuncSetAttribute(attn_score, cudaFuncAttributeMaxDynamicSharedMemorySize,
                         SMEM_BYTES);

    dim3 gridA(NT * NT, Bb);                       // all (qt,kt); upper tiles zero-fill
    attn_score<<<gridA, 256, SMEM_BYTES>>>(Q, K, V, out_w);

    finalize<<<(Bb * Ss * Dh / 4) / 256, 256>>>(out_vec);
}